// round 1
// baseline (speedup 1.0000x reference)
#include <cuda_runtime.h>

#define B 1024
#define D1 200
#define N_ENT 100000
#define NE_P 100096          // N_ENT padded to multiple of 128
#define RDIM 288
#define OC 32
#define FW 9
#define OH 10
#define OW 12
#define SP 120               // OH*OW
#define FCL 3840             // OC*SP
#define EPS 1e-5f

// ---------------- device scratch (static, zero-init at module load) ----------
__device__ float g_y[B * FCL];          // conv output [b][oc*120+sp]
__device__ float g_z[B * D1];           // fc output [b][d]
__device__ float g_Ht[D1 * B];          // relu(bn2(z)) transposed: [d][b]
__device__ float g_Et[D1 * NE_P];       // E_w transposed k-major: [d][n], zero padded
__device__ float g_stats0[2];           // bn0 sum, sumsq
__device__ float g_stats1[2 * OC];      // bn1 per-channel sum, sumsq
__device__ float g_aff2[2 * D1];        // bn2 scale[d], shift[d]

// ---------------- K0: zero the atomic accumulators --------------------------
__global__ void k0_zero() {
    int i = threadIdx.x;
    if (i < 2) g_stats0[i] = 0.f;
    if (i < 2 * OC) g_stats1[i] = 0.f;
}

// ---------------- K1: bn0 statistics over gathered rows ---------------------
__global__ void k1_stats0(const int* __restrict__ e1_idx, const float* __restrict__ E) {
    int tid = blockIdx.x * blockDim.x + threadIdx.x;
    int stride = gridDim.x * blockDim.x;
    float s = 0.f, q = 0.f;
    for (int i = tid; i < B * D1; i += stride) {
        int b = i / D1;
        int d = i - b * D1;
        float v = E[(size_t)e1_idx[b] * D1 + d];
        s += v; q += v * v;
    }
    #pragma unroll
    for (int o = 16; o > 0; o >>= 1) {
        s += __shfl_xor_sync(0xffffffffu, s, o);
        q += __shfl_xor_sync(0xffffffffu, q, o);
    }
    __shared__ float ss[8], qs[8];
    int w = threadIdx.x >> 5, l = threadIdx.x & 31;
    if (l == 0) { ss[w] = s; qs[w] = q; }
    __syncthreads();
    if (threadIdx.x == 0) {
        float S = 0.f, Q = 0.f;
        for (int i = 0; i < (int)(blockDim.x >> 5); i++) { S += ss[i]; Q += qs[i]; }
        atomicAdd(&g_stats0[0], S);
        atomicAdd(&g_stats0[1], Q);
    }
}

// ---------------- K_transE: E_w [n][k] -> g_Et [k][n] ------------------------
__global__ void k_transE(const float* __restrict__ E) {
    __shared__ float t[32][33];
    int nb = blockIdx.x * 32, kb = blockIdx.y * 32;
    int x = threadIdx.x, y = threadIdx.y;      // 32 x 8
    for (int i = y; i < 32; i += 8) {
        int n = nb + i, k = kb + x;
        t[i][x] = (n < N_ENT && k < D1) ? E[(size_t)n * D1 + k] : 0.f;
    }
    __syncthreads();
    for (int i = y; i < 32; i += 8) {
        int k = kb + i, n = nb + x;
        if (n < N_ENT && k < D1) g_Et[(size_t)k * NE_P + n] = t[x][i];
    }
}

// ---------------- K2: bn0-normalize + per-sample 1x9 conv + bn1 stats --------
__global__ void k2_conv(const int* __restrict__ e1_idx, const int* __restrict__ r_idx,
                        const float* __restrict__ E, const float* __restrict__ R,
                        const float* __restrict__ bn0_g, const float* __restrict__ bn0_b) {
    __shared__ float xs[D1];
    __shared__ float ks[RDIM];
    int b = blockIdx.x;
    int tid = threadIdx.x;                 // 128 threads
    float cnt0 = (float)(B * D1);
    float m0 = g_stats0[0] / cnt0;
    float v0 = g_stats0[1] / cnt0 - m0 * m0;
    float a0 = rsqrtf(v0 + EPS) * bn0_g[0];
    float c0 = bn0_b[0] - m0 * a0;
    int e1 = e1_idx[b], rr = r_idx[b];
    for (int i = tid; i < D1; i += 128)  xs[i] = E[(size_t)e1 * D1 + i] * a0 + c0;
    for (int i = tid; i < RDIM; i += 128) ks[i] = R[(size_t)rr * RDIM + i];
    __syncthreads();

    int oc = tid >> 2, q = tid & 3;        // 32 channels x 4 threads each
    float kf[FW];
    #pragma unroll
    for (int t = 0; t < FW; t++) kf[t] = ks[oc * FW + t];
    float s = 0.f, qq = 0.f;
    for (int si = 0; si < 30; si++) {
        int sp = q * 30 + si;
        int oh = sp / OW, ow = sp - oh * OW;
        const float* xr = &xs[oh * 20 + ow];
        float acc = 0.f;
        #pragma unroll
        for (int t = 0; t < FW; t++) acc += xr[t] * kf[t];
        g_y[(size_t)b * FCL + oc * SP + sp] = acc;
        s += acc; qq += acc * acc;
    }
    s  += __shfl_xor_sync(0xffffffffu, s, 1);
    s  += __shfl_xor_sync(0xffffffffu, s, 2);
    qq += __shfl_xor_sync(0xffffffffu, qq, 1);
    qq += __shfl_xor_sync(0xffffffffu, qq, 2);
    if (q == 0) {
        atomicAdd(&g_stats1[oc], s);
        atomicAdd(&g_stats1[OC + oc], qq);
    }
}

// ---------------- K3: bn1-fold + FC GEMM  z = yn @ fc_w^T + fc_b -------------
#define K3_BM 64
#define K3_BN 64
#define K3_BK 32
__global__ void k3_fc(const float* __restrict__ fc_w, const float* __restrict__ fc_b,
                      const float* __restrict__ bn1_g, const float* __restrict__ bn1_b) {
    __shared__ float Ys[K3_BM][K3_BK + 1];
    __shared__ float Ws[K3_BN][K3_BK + 1];
    __shared__ float al[OC], be[OC];
    int tid = threadIdx.x;                 // 256 threads
    if (tid < OC) {
        float cnt = (float)(B * SP);
        float m = g_stats1[tid] / cnt;
        float v = g_stats1[OC + tid] / cnt - m * m;
        float a = rsqrtf(v + EPS) * bn1_g[tid];
        al[tid] = a;
        be[tid] = bn1_b[tid] - m * a;
    }
    __syncthreads();
    int b0 = blockIdx.y * K3_BM;
    int d0 = blockIdx.x * K3_BN;
    int tx = tid & 15, ty = tid >> 4;      // 16 x 16
    float acc[4][4] = {};
    for (int k0 = 0; k0 < FCL; k0 += K3_BK) {
        for (int i = tid; i < K3_BM * K3_BK; i += 256) {
            int r = i >> 5, c = i & 31;
            int j = k0 + c;
            float v = g_y[(size_t)(b0 + r) * FCL + j];
            int ch = j / SP;
            Ys[r][c] = v * al[ch] + be[ch];
        }
        for (int i = tid; i < K3_BN * K3_BK; i += 256) {
            int r = i >> 5, c = i & 31;
            int d = d0 + r;
            Ws[r][c] = (d < D1) ? fc_w[(size_t)d * FCL + k0 + c] : 0.f;
        }
        __syncthreads();
        #pragma unroll
        for (int kk = 0; kk < K3_BK; kk++) {
            float a[4], w[4];
            #pragma unroll
            for (int i = 0; i < 4; i++) a[i] = Ys[ty * 4 + i][kk];
            #pragma unroll
            for (int i = 0; i < 4; i++) w[i] = Ws[tx * 4 + i][kk];
            #pragma unroll
            for (int i = 0; i < 4; i++)
                #pragma unroll
                for (int j = 0; j < 4; j++)
                    acc[i][j] += a[i] * w[j];
        }
        __syncthreads();
    }
    for (int i = 0; i < 4; i++) {
        int b = b0 + ty * 4 + i;
        for (int j = 0; j < 4; j++) {
            int d = d0 + tx * 4 + j;
            if (d < D1) g_z[(size_t)b * D1 + d] = acc[i][j] + fc_b[d];
        }
    }
}

// ---------------- K4: bn2 per-feature stats -> scale/shift -------------------
__global__ void k4_bn2(const float* __restrict__ bn2_g, const float* __restrict__ bn2_b) {
    int d = blockIdx.x;
    int tid = threadIdx.x;
    float s = 0.f, q = 0.f;
    for (int b = tid; b < B; b += blockDim.x) {
        float v = g_z[(size_t)b * D1 + d];
        s += v; q += v * v;
    }
    __shared__ float ss[256], qs[256];
    ss[tid] = s; qs[tid] = q;
    __syncthreads();
    for (int o = 128; o > 0; o >>= 1) {
        if (tid < o) { ss[tid] += ss[tid + o]; qs[tid] += qs[tid + o]; }
        __syncthreads();
    }
    if (tid == 0) {
        float m = ss[0] / (float)B;
        float v = qs[0] / (float)B - m * m;
        float sc = rsqrtf(v + EPS) * bn2_g[d];
        g_aff2[d] = sc;
        g_aff2[D1 + d] = bn2_b[d] - m * sc;
    }
}

// ---------------- K4b: Ht[d][b] = relu(bn2(z)) -------------------------------
__global__ void k4b_ht() {
    int i = blockIdx.x * blockDim.x + threadIdx.x;   // i = d*B + b
    if (i < B * D1) {
        int d = i >> 10;          // /1024
        int b = i & 1023;
        float v = g_z[(size_t)b * D1 + d];
        g_Ht[i] = fmaxf(0.f, v * g_aff2[d] + g_aff2[D1 + d]);
    }
}

// ---------------- K5: big GEMM + bias + sigmoid -------------------------------
// out[b][n] = sigmoid( sum_d Ht[d][b] * Et[d][n] + bias[n] )
#define K5_BN 128     // entities per block
#define K5_BB 64      // batch per block
__global__ void k5_big(const float* __restrict__ bias, float* __restrict__ out) {
    extern __shared__ float smem[];
    float* Es = smem;                         // [D1][K5_BN]
    float* Hs = smem + D1 * K5_BN;            // [D1][K5_BB]
    int b0 = blockIdx.x * K5_BB;              // batch fastest -> E tile L2 reuse
    int n0 = blockIdx.y * K5_BN;
    int tid = threadIdx.x;                    // 256 threads

    for (int i = tid; i < D1 * (K5_BN / 4); i += 256) {
        int k = i >> 5;            // 32 float4 per row
        int c = (i & 31) << 2;
        *(float4*)&Es[k * K5_BN + c] = *(const float4*)&g_Et[(size_t)k * NE_P + n0 + c];
    }
    for (int i = tid; i < D1 * (K5_BB / 4); i += 256) {
        int k = i >> 4;            // 16 float4 per row
        int c = (i & 15) << 2;
        *(float4*)&Hs[k * K5_BB + c] = *(const float4*)&g_Ht[(size_t)k * B + b0 + c];
    }
    __syncthreads();

    int tn = tid & 15;            // 16 n-groups * 8 = 128
    int tb = tid >> 4;            // 16 b-groups * 4 = 64
    int nn = tn * 8, bb = tb * 4;
    float acc[4][8] = {};
    #pragma unroll 2
    for (int k = 0; k < D1; k++) {
        float e[8], h[4];
        *(float4*)&e[0] = *(float4*)&Es[k * K5_BN + nn];
        *(float4*)&e[4] = *(float4*)&Es[k * K5_BN + nn + 4];
        *(float4*)&h[0] = *(float4*)&Hs[k * K5_BB + bb];
        #pragma unroll
        for (int i = 0; i < 4; i++)
            #pragma unroll
            for (int j = 0; j < 8; j++)
                acc[i][j] += h[i] * e[j];
    }

    int nbase = n0 + nn;
    float bs[8];
    #pragma unroll
    for (int j = 0; j < 8; j++) {
        int n = nbase + j;
        bs[j] = (n < N_ENT) ? bias[n] : 0.f;
    }
    for (int i = 0; i < 4; i++) {
        int b = b0 + bb + i;
        float r[8];
        #pragma unroll
        for (int j = 0; j < 8; j++) {
            float sc = acc[i][j] + bs[j];
            r[j] = 1.f / (1.f + __expf(-sc));
        }
        size_t base = (size_t)b * N_ENT + nbase;
        if (nbase + 7 < N_ENT) {
            *(float4*)&out[base]     = make_float4(r[0], r[1], r[2], r[3]);
            *(float4*)&out[base + 4] = make_float4(r[4], r[5], r[6], r[7]);
        } else {
            for (int j = 0; j < 8; j++)
                if (nbase + j < N_ENT) out[base + j] = r[j];
        }
    }
}

// ---------------- launch -------------------------------------------------------
extern "C" void kernel_launch(void* const* d_in, const int* in_sizes, int n_in,
                              void* d_out, int out_size) {
    const int*   e1_idx = (const int*)d_in[0];
    const int*   r_idx  = (const int*)d_in[1];
    const float* E_w    = (const float*)d_in[2];
    const float* R_w    = (const float*)d_in[3];
    const float* fc_w   = (const float*)d_in[4];
    const float* fc_b   = (const float*)d_in[5];
    const float* bn0_g  = (const float*)d_in[6];
    const float* bn0_b  = (const float*)d_in[7];
    const float* bn1_g  = (const float*)d_in[8];
    const float* bn1_b  = (const float*)d_in[9];
    const float* bn2_g  = (const float*)d_in[10];
    const float* bn2_b  = (const float*)d_in[11];
    const float* b_bias = (const float*)d_in[12];
    float* out = (float*)d_out;

    int k5_smem = (D1 * K5_BN + D1 * K5_BB) * (int)sizeof(float);   // 153600
    cudaFuncSetAttribute(k5_big, cudaFuncAttributeMaxDynamicSharedMemorySize, k5_smem);

    k0_zero<<<1, 64>>>();
    k1_stats0<<<128, 256>>>(e1_idx, E_w);
    k_transE<<<dim3((N_ENT + 31) / 32, (D1 + 31) / 32), dim3(32, 8)>>>(E_w);
    k2_conv<<<B, 128>>>(e1_idx, r_idx, E_w, R_w, bn0_g, bn0_b);
    k3_fc<<<dim3((D1 + K3_BN - 1) / K3_BN, B / K3_BM), 256>>>(fc_w, fc_b, bn1_g, bn1_b);
    k4_bn2<<<D1, 256>>>(bn2_g, bn2_b);
    k4b_ht<<<(B * D1 + 255) / 256, 256>>>();
    k5_big<<<dim3(B / K5_BB, NE_P / K5_BN), 256, k5_smem>>>(b_bias, out);
}

// round 3
// speedup vs baseline: 1.7772x; 1.7772x over previous
#include <cuda_runtime.h>
#include <cuda_bf16.h>
#include <cstdint>

#define B 1024
#define D1 200
#define N_ENT 100000
#define RDIM 288
#define OC 32
#define FW 9
#define OH 10
#define OW 12
#define SP 120
#define FCL 3840
#define EPS 1e-5f

#define KP 208                 // K padded per section (26 x 8)
#define NE128 100096           // N_ENT padded to 128
#define NT 782                 // n-tiles of 128
#define NIT 10                 // k-iterations of BK=64 (640 total, 624 valid)

// ---------------- device scratch ----------------
__device__ float g_y[B * FCL];
__device__ float g_z[B * D1];
__device__ float g_stats0[2];
__device__ float g_stats1[2 * OC];
__device__ float g_aff2[2 * D1];
__device__ __nv_bfloat16 g_Ebf_hi[(size_t)NE128 * KP];
__device__ __nv_bfloat16 g_Ebf_lo[(size_t)NE128 * KP];
__device__ __nv_bfloat16 g_Hbf_hi[(size_t)B * KP];
__device__ __nv_bfloat16 g_Hbf_lo[(size_t)B * KP];
__device__ __align__(16) char g_zero16[16];   // static zero-init

// ================= helpers =================
__device__ __forceinline__ uint32_t smem_u32(const void* p) {
    uint32_t a;
    asm("{ .reg .u64 t; cvta.to.shared.u64 t, %1; cvt.u32.u64 %0, t; }" : "=r"(a) : "l"(p));
    return a;
}
__device__ __forceinline__ void cpa16(uint32_t dst, const void* src) {
    asm volatile("cp.async.cg.shared.global [%0], [%1], 16;" :: "r"(dst), "l"(src));
}
__device__ __forceinline__ void ldsm4(uint32_t* r, uint32_t a) {
    asm volatile("ldmatrix.sync.aligned.m8n8.x4.shared.b16 {%0,%1,%2,%3}, [%4];"
        : "=r"(r[0]), "=r"(r[1]), "=r"(r[2]), "=r"(r[3]) : "r"(a));
}
__device__ __forceinline__ void mma_bf16(float* c, const uint32_t* a, const uint32_t* b) {
    asm volatile("mma.sync.aligned.m16n8k16.row.col.f32.bf16.bf16.f32 "
        "{%0,%1,%2,%3}, {%4,%5,%6,%7}, {%8,%9}, {%0,%1,%2,%3};"
        : "+f"(c[0]), "+f"(c[1]), "+f"(c[2]), "+f"(c[3])
        : "r"(a[0]), "r"(a[1]), "r"(a[2]), "r"(a[3]), "r"(b[0]), "r"(b[1]));
}

// ---------------- K0: zero accumulators ----------------
__global__ void k0_zero() {
    int i = threadIdx.x;
    if (i < 2) g_stats0[i] = 0.f;
    if (i < 2 * OC) g_stats1[i] = 0.f;
}

// ---------------- K1: bn0 stats ----------------
__global__ void k1_stats0(const int* __restrict__ e1_idx, const float* __restrict__ E) {
    int tid = blockIdx.x * blockDim.x + threadIdx.x;
    int stride = gridDim.x * blockDim.x;
    float s = 0.f, q = 0.f;
    for (int i = tid; i < B * D1; i += stride) {
        int b = i / D1;
        float v = E[(size_t)e1_idx[b] * D1 + (i - b * D1)];
        s += v; q += v * v;
    }
    #pragma unroll
    for (int o = 16; o > 0; o >>= 1) {
        s += __shfl_xor_sync(0xffffffffu, s, o);
        q += __shfl_xor_sync(0xffffffffu, q, o);
    }
    __shared__ float ss[8], qs[8];
    int w = threadIdx.x >> 5, l = threadIdx.x & 31;
    if (l == 0) { ss[w] = s; qs[w] = q; }
    __syncthreads();
    if (threadIdx.x == 0) {
        float S = 0.f, Q = 0.f;
        for (int i = 0; i < (int)(blockDim.x >> 5); i++) { S += ss[i]; Q += qs[i]; }
        atomicAdd(&g_stats0[0], S);
        atomicAdd(&g_stats0[1], Q);
    }
}

// ---------------- prep_E: E_w -> bf16 hi/lo, k-padded ----------------
__global__ void prep_E(const float* __restrict__ E) {
    int i = blockIdx.x * blockDim.x + threadIdx.x;
    if (i >= NE128 * KP) return;
    int r = i / KP, k = i - r * KP;
    float v = (r < N_ENT && k < D1) ? E[(size_t)r * D1 + k] : 0.f;
    __nv_bfloat16 h = __float2bfloat16(v);
    g_Ebf_hi[i] = h;
    g_Ebf_lo[i] = __float2bfloat16(v - __bfloat162float(h));
}

// ---------------- K2: bn0 + per-sample conv + bn1 stats ----------------
__global__ void k2_conv(const int* __restrict__ e1_idx, const int* __restrict__ r_idx,
                        const float* __restrict__ E, const float* __restrict__ R,
                        const float* __restrict__ bn0_g, const float* __restrict__ bn0_b) {
    __shared__ float xs[D1];
    __shared__ float ks[RDIM];
    int b = blockIdx.x;
    int tid = threadIdx.x;
    float cnt0 = (float)(B * D1);
    float m0 = g_stats0[0] / cnt0;
    float v0 = g_stats0[1] / cnt0 - m0 * m0;
    float a0 = rsqrtf(v0 + EPS) * bn0_g[0];
    float c0 = bn0_b[0] - m0 * a0;
    int e1 = e1_idx[b], rr = r_idx[b];
    for (int i = tid; i < D1; i += 128)  xs[i] = E[(size_t)e1 * D1 + i] * a0 + c0;
    for (int i = tid; i < RDIM; i += 128) ks[i] = R[(size_t)rr * RDIM + i];
    __syncthreads();

    int oc = tid >> 2, q = tid & 3;
    float kf[FW];
    #pragma unroll
    for (int t = 0; t < FW; t++) kf[t] = ks[oc * FW + t];
    float s = 0.f, qq = 0.f;
    for (int si = 0; si < 30; si++) {
        int sp = q * 30 + si;
        int oh = sp / OW, ow = sp - oh * OW;
        const float* xr = &xs[oh * 20 + ow];
        float acc = 0.f;
        #pragma unroll
        for (int t = 0; t < FW; t++) acc += xr[t] * kf[t];
        g_y[(size_t)b * FCL + oc * SP + sp] = acc;
        s += acc; qq += acc * acc;
    }
    s  += __shfl_xor_sync(0xffffffffu, s, 1);
    s  += __shfl_xor_sync(0xffffffffu, s, 2);
    qq += __shfl_xor_sync(0xffffffffu, qq, 1);
    qq += __shfl_xor_sync(0xffffffffu, qq, 2);
    if (q == 0) {
        atomicAdd(&g_stats1[oc], s);
        atomicAdd(&g_stats1[OC + oc], qq);
    }
}

// ---------------- K3: bn1-fold + FC GEMM ----------------
#define K3_BM 64
#define K3_BN 64
#define K3_BK 32
__global__ void k3_fc(const float* __restrict__ fc_w, const float* __restrict__ fc_b,
                      const float* __restrict__ bn1_g, const float* __restrict__ bn1_b) {
    __shared__ float Ys[K3_BM][K3_BK + 1];
    __shared__ float Ws[K3_BN][K3_BK + 1];
    __shared__ float al[OC], be[OC];
    int tid = threadIdx.x;
    if (tid < OC) {
        float cnt = (float)(B * SP);
        float m = g_stats1[tid] / cnt;
        float v = g_stats1[OC + tid] / cnt - m * m;
        float a = rsqrtf(v + EPS) * bn1_g[tid];
        al[tid] = a;
        be[tid] = bn1_b[tid] - m * a;
    }
    __syncthreads();
    int b0 = blockIdx.y * K3_BM;
    int d0 = blockIdx.x * K3_BN;
    int tx = tid & 15, ty = tid >> 4;
    float acc[4][4] = {};
    for (int k0 = 0; k0 < FCL; k0 += K3_BK) {
        for (int i = tid; i < K3_BM * K3_BK; i += 256) {
            int r = i >> 5, c = i & 31;
            int j = k0 + c;
            float v = g_y[(size_t)(b0 + r) * FCL + j];
            int ch = j / SP;
            Ys[r][c] = v * al[ch] + be[ch];
        }
        for (int i = tid; i < K3_BN * K3_BK; i += 256) {
            int r = i >> 5, c = i & 31;
            int d = d0 + r;
            Ws[r][c] = (d < D1) ? fc_w[(size_t)d * FCL + k0 + c] : 0.f;
        }
        __syncthreads();
        #pragma unroll
        for (int kk = 0; kk < K3_BK; kk++) {
            float a[4], w[4];
            #pragma unroll
            for (int i = 0; i < 4; i++) a[i] = Ys[ty * 4 + i][kk];
            #pragma unroll
            for (int i = 0; i < 4; i++) w[i] = Ws[tx * 4 + i][kk];
            #pragma unroll
            for (int i = 0; i < 4; i++)
                #pragma unroll
                for (int j = 0; j < 4; j++)
                    acc[i][j] += a[i] * w[j];
        }
        __syncthreads();
    }
    for (int i = 0; i < 4; i++) {
        int b = b0 + ty * 4 + i;
        for (int j = 0; j < 4; j++) {
            int d = d0 + tx * 4 + j;
            if (d < D1) g_z[(size_t)b * D1 + d] = acc[i][j] + fc_b[d];
        }
    }
}

// ---------------- K4: bn2 stats -> scale/shift ----------------
__global__ void k4_bn2(const float* __restrict__ bn2_g, const float* __restrict__ bn2_b) {
    int d = blockIdx.x;
    int tid = threadIdx.x;
    float s = 0.f, q = 0.f;
    for (int b = tid; b < B; b += blockDim.x) {
        float v = g_z[(size_t)b * D1 + d];
        s += v; q += v * v;
    }
    __shared__ float ss[256], qs[256];
    ss[tid] = s; qs[tid] = q;
    __syncthreads();
    for (int o = 128; o > 0; o >>= 1) {
        if (tid < o) { ss[tid] += ss[tid + o]; qs[tid] += qs[tid + o]; }
        __syncthreads();
    }
    if (tid == 0) {
        float m = ss[0] / (float)B;
        float v = qs[0] / (float)B - m * m;
        float sc = rsqrtf(v + EPS) * bn2_g[d];
        g_aff2[d] = sc;
        g_aff2[D1 + d] = bn2_b[d] - m * sc;
    }
}

// ---------------- prep_H: relu(bn2(z)) -> bf16 hi/lo ----------------
__global__ void prep_H() {
    int i = blockIdx.x * blockDim.x + threadIdx.x;
    if (i >= B * KP) return;
    int b = i / KP, k = i - b * KP;
    float v = 0.f;
    if (k < D1) {
        v = g_z[(size_t)b * D1 + k] * g_aff2[k] + g_aff2[D1 + k];
        v = fmaxf(v, 0.f);
    }
    __nv_bfloat16 h = __float2bfloat16(v);
    g_Hbf_hi[i] = h;
    g_Hbf_lo[i] = __float2bfloat16(v - __bfloat162float(h));
}

// ---------------- K5: mma.sync bf16 GEMM + bias + sigmoid ----------------
// C[1024, 100096] = A[1024, 624] x B[100096, 624]^T   (virtual K sections:
//  k 0..207: H_hi . E_hi | 208..415: H_lo . E_hi | 416..623: H_hi . E_lo)
// CTA: 128x128, 256 threads, warp tile 64x32, BK=64, 3-stage cp.async pipe.
#define STAGE_BYTES 32768   // A 16KB + B 16KB
__global__ void __launch_bounds__(256, 1)
k5_mma(const float* __restrict__ bias, float* __restrict__ out) {
    extern __shared__ char sm[];
    __shared__ float s_bias[128];

    const int tid = threadIdx.x;
    const int lane = tid & 31;
    const int warp = tid >> 5;
    const int b0 = blockIdx.x << 7;
    const int n0 = blockIdx.y << 7;
    const uint32_t sm0 = smem_u32(sm);

    if (tid < 128) {
        int n = n0 + tid;
        s_bias[tid] = (n < N_ENT) ? bias[n] : 0.f;
    }

    // ---- loader setup: thread t loads row t>>1, 4 chunks (t&1)*4.. ----
    const int lrow = tid >> 1;
    const int lc4 = (tid & 1) << 2;
    const uint32_t lsw = (uint32_t)(lrow & 7);
    const char* aHi = (const char*)g_Hbf_hi + (size_t)(b0 + lrow) * (KP * 2);
    const char* aLo = (const char*)g_Hbf_lo + (size_t)(b0 + lrow) * (KP * 2);
    const char* bHi = (const char*)g_Ebf_hi + (size_t)(n0 + lrow) * (KP * 2);
    const char* bLo = (const char*)g_Ebf_lo + (size_t)(n0 + lrow) * (KP * 2);
    const uint32_t dstRow = sm0 + (uint32_t)lrow * 128;

    auto issue = [&](int it) {
        uint32_t base = dstRow + (uint32_t)(it % 3) * STAGE_BYTES;
        #pragma unroll
        for (int j = 0; j < 4; j++) {
            int gc = it * 8 + lc4 + j;                 // global k-chunk 0..79
            uint32_t sw = (uint32_t)(((lc4 + j) ^ lsw) << 4);
            const char *pa, *pb;
            if (gc < 26)      { pa = aHi + gc * 16;        pb = bHi + gc * 16; }
            else if (gc < 52) { pa = aLo + (gc - 26) * 16; pb = bHi + (gc - 26) * 16; }
            else if (gc < 78) { pa = aHi + (gc - 52) * 16; pb = bLo + (gc - 52) * 16; }
            else              { pa = g_zero16;             pb = g_zero16; }
            cpa16(base + sw, pa);
            cpa16(base + 16384 + sw, pb);
        }
        asm volatile("cp.async.commit_group;" ::: "memory");
    };

    // ---- mma setup ----
    const int wm = (warp & 1) << 6;          // 0 / 64
    const int wn = (warp >> 1) << 5;         // 0..96
    const uint32_t axor = (uint32_t)(lane & 7);
    const uint32_t aRowOff = (uint32_t)(wm + (lane & 15)) * 128;
    const uint32_t aChunkBase = (uint32_t)(lane >> 4);            // 0/1
    const uint32_t bRow0 = (uint32_t)(wn + (lane & 7) + ((lane >> 4) << 3));
    const uint32_t bChunkBase = (uint32_t)((lane >> 3) & 1);

    float acc[16][4] = {};

    issue(0); issue(1); issue(2);

    #pragma unroll 1
    for (int it = 0; it < NIT; it++) {
        asm volatile("cp.async.wait_group 2;" ::: "memory");
        __syncthreads();
        uint32_t sA = sm0 + (uint32_t)(it % 3) * STAGE_BYTES;
        uint32_t sB = sA + 16384;
        #pragma unroll
        for (int ks = 0; ks < 4; ks++) {
            uint32_t a[4][4];
            #pragma unroll
            for (int mi = 0; mi < 4; mi++) {
                uint32_t ch = (uint32_t)(ks * 2) + aChunkBase;
                uint32_t addr = sA + aRowOff + (uint32_t)(mi << 11) + ((ch ^ axor) << 4);
                ldsm4(a[mi], addr);
            }
            uint32_t b[2][4];
            #pragma unroll
            for (int nj = 0; nj < 2; nj++) {
                uint32_t ch = (uint32_t)(ks * 2) + bChunkBase;
                uint32_t addr = sB + (bRow0 + (uint32_t)(nj << 4)) * 128 + ((ch ^ axor) << 4);
                ldsm4(b[nj], addr);
            }
            #pragma unroll
            for (int mi = 0; mi < 4; mi++)
                #pragma unroll
                for (int nt = 0; nt < 4; nt++)
                    mma_bf16(acc[mi * 4 + nt], a[mi], &b[nt >> 1][(nt & 1) << 1]);
        }
        __syncthreads();
        if (it + 3 < NIT) issue(it + 3);
        else asm volatile("cp.async.commit_group;" ::: "memory");
    }

    // ---- epilogue: bias + sigmoid + store ----
    const int r = lane >> 2;
    const int cn = (lane & 3) << 1;
    #pragma unroll
    for (int mi = 0; mi < 4; mi++) {
        #pragma unroll
        for (int half = 0; half < 2; half++) {
            int mrow = b0 + wm + mi * 16 + r + half * 8;
            float* orow = out + (size_t)mrow * N_ENT;
            #pragma unroll
            for (int nt = 0; nt < 4; nt++) {
                int nloc = wn + nt * 8 + cn;
                int n = n0 + nloc;
                float x0 = acc[mi * 4 + nt][half * 2 + 0] + s_bias[nloc];
                float x1 = acc[mi * 4 + nt][half * 2 + 1] + s_bias[nloc + 1];
                float v0 = __fdividef(1.f, 1.f + __expf(-x0));
                float v1 = __fdividef(1.f, 1.f + __expf(-x1));
                if (n + 1 < N_ENT) {
                    *(float2*)(orow + n) = make_float2(v0, v1);
                } else if (n < N_ENT) {
                    orow[n] = v0;
                }
            }
        }
    }
}

// ---------------- launch ----------------
extern "C" void kernel_launch(void* const* d_in, const int* in_sizes, int n_in,
                              void* d_out, int out_size) {
    const int*   e1_idx = (const int*)d_in[0];
    const int*   r_idx  = (const int*)d_in[1];
    const float* E_w    = (const float*)d_in[2];
    const float* R_w    = (const float*)d_in[3];
    const float* fc_w   = (const float*)d_in[4];
    const float* fc_b   = (const float*)d_in[5];
    const float* bn1_g  = (const float*)d_in[8];
    const float* bn1_b  = (const float*)d_in[9];
    const float* bn0_g  = (const float*)d_in[6];
    const float* bn0_b  = (const float*)d_in[7];
    const float* bn2_g  = (const float*)d_in[10];
    const float* bn2_b  = (const float*)d_in[11];
    const float* b_bias = (const float*)d_in[12];
    float* out = (float*)d_out;

    int k5_smem = 3 * STAGE_BYTES;
    cudaFuncSetAttribute(k5_mma, cudaFuncAttributeMaxDynamicSharedMemorySize, k5_smem);

    k0_zero<<<1, 64>>>();
    k1_stats0<<<128, 256>>>(e1_idx, E_w);
    prep_E<<<(NE128 * KP + 255) / 256, 256>>>(E_w);
    k2_conv<<<B, 128>>>(e1_idx, r_idx, E_w, R_w, bn0_g, bn0_b);
    k3_fc<<<dim3((D1 + K3_BN - 1) / K3_BN, B / K3_BM), 256>>>(fc_w, fc_b, bn1_g, bn1_b);
    k4_bn2<<<D1, 256>>>(bn2_g, bn2_b);
    prep_H<<<(B * KP + 255) / 256, 256>>>();
    k5_mma<<<dim3(B / 128, NT), 256, k5_smem>>>(b_bias, out);
}